// round 1
// baseline (speedup 1.0000x reference)
#include <cuda_runtime.h>
#include <math.h>

#define BATCH 4
#define SEQ   1024
#define HID   1024
#define NHEAD 16
#define HDIM  64
#define SCALE 0.125f

// Scratch (device globals are the sanctioned alloc-free workaround)
__device__ float g_Q[BATCH*NHEAD*SEQ*HDIM];   // [b][h][s][d]
__device__ float g_K[BATCH*NHEAD*SEQ*HDIM];
__device__ float g_V[BATCH*NHEAD*SEQ*HDIM];
__device__ float g_ctx[BATCH*SEQ*HID];        // [b][s][h*64+d]
__device__ int   g_nearest[BATCH*SEQ];
__device__ float g_colbias[BATCH*SEQ];

// ---------------------------------------------------------------------------
// Morphological bias precompute: nearest verb (argmin ties -> smallest j),
// column bias = 0.75*(type==0) + 0.36*(type==1)
// ---------------------------------------------------------------------------
__global__ void bias_kernel(const int* __restrict__ morpho)
{
    int b = blockIdx.x;
    __shared__ int types[SEQ];
    for (int i = threadIdx.x; i < SEQ; i += blockDim.x)
        types[i] = morpho[b*SEQ + i];
    __syncthreads();
    for (int q = threadIdx.x; q < SEQ; q += blockDim.x) {
        int best = -1;
        int bestd = 1 << 30;
        for (int j = 0; j < SEQ; j++) {
            if (types[j] == 2) {
                int d = abs(q - j);
                if (d < bestd) { bestd = d; best = j; }
            }
        }
        g_nearest[b*SEQ + q] = best;          // -1 => no verb in batch
        int t = types[q];
        float cb = 0.0f;
        if (t == 0) cb = 0.75f;               // ROOT_BIAS * 0.5
        else if (t == 1) cb = 0.36f;          // SUFFIX_BIAS * 0.3
        g_colbias[b*SEQ + q] = cb;
    }
}

// ---------------------------------------------------------------------------
// fp32 GEMM: C = A[M,1024] @ W[1024,1024] + bias.  128x128x8 tile, 256 thr,
// 8x8 microtile (split 4+4 halves for conflict-free float4 SMEM reads).
// mode 0: scatter to [b][h][s][d] (QKV);  mode 1: plain row-major [M,N].
// ---------------------------------------------------------------------------
__global__ void __launch_bounds__(256) gemm128(
    const float* __restrict__ A, const float* __restrict__ W,
    const float* __restrict__ bias, float* __restrict__ C, int mode)
{
    const int K = 1024, N = 1024;
    __shared__ float As[8][128];
    __shared__ float Bs[8][128];
    int bm = blockIdx.y * 128, bn = blockIdx.x * 128;
    int tid = threadIdx.x;
    int tx = tid & 15, ty = tid >> 4;

    float acc[8][8];
#pragma unroll
    for (int i = 0; i < 8; i++)
#pragma unroll
        for (int j = 0; j < 8; j++) acc[i][j] = 0.f;

    int ar = tid >> 1, ac = (tid & 1) * 4;   // A tile load coords
    int br = tid >> 5, bc = (tid & 31) * 4;  // B tile load coords

    for (int k0 = 0; k0 < K; k0 += 8) {
        float4 av = *(const float4*)&A[(size_t)(bm + ar) * K + k0 + ac];
        As[ac + 0][ar] = av.x; As[ac + 1][ar] = av.y;
        As[ac + 2][ar] = av.z; As[ac + 3][ar] = av.w;
        *(float4*)&Bs[br][bc] = *(const float4*)&W[(size_t)(k0 + br) * N + bn + bc];
        __syncthreads();
#pragma unroll
        for (int k = 0; k < 8; k++) {
            float4 a0 = *(const float4*)&As[k][ty * 4];
            float4 a1 = *(const float4*)&As[k][64 + ty * 4];
            float4 b0 = *(const float4*)&Bs[k][tx * 4];
            float4 b1 = *(const float4*)&Bs[k][64 + tx * 4];
            float ra[8] = {a0.x, a0.y, a0.z, a0.w, a1.x, a1.y, a1.z, a1.w};
            float rb[8] = {b0.x, b0.y, b0.z, b0.w, b1.x, b1.y, b1.z, b1.w};
#pragma unroll
            for (int i = 0; i < 8; i++)
#pragma unroll
                for (int j = 0; j < 8; j++)
                    acc[i][j] += ra[i] * rb[j];
        }
        __syncthreads();
    }

#pragma unroll
    for (int i = 0; i < 8; i++) {
        int rl = (i < 4) ? (ty * 4 + i) : (64 + ty * 4 + (i - 4));
        int gm = bm + rl;
#pragma unroll
        for (int j = 0; j < 8; j++) {
            int cl = (j < 4) ? (tx * 4 + j) : (64 + tx * 4 + (j - 4));
            int gn = bn + cl;
            float v = acc[i][j] + bias[gn];
            if (mode == 0) {
                int bb = gm >> 10, s = gm & 1023;
                int h = gn >> 6,  d = gn & 63;
                C[((size_t)((bb * NHEAD + h) * SEQ) + s) * HDIM + d] = v;
            } else {
                C[(size_t)gm * N + gn] = v;
            }
        }
    }
}

// ---------------------------------------------------------------------------
// Flash-style attention, fp32. 128 q-rows per CTA, 1 row per thread.
// K/V tiles 32x64 in SMEM; online softmax; morpho bias folded into scores.
// Writes context in [B,S,H] layout for the output projection.
// ---------------------------------------------------------------------------
__global__ void __launch_bounds__(128) attn_kernel(
    const float* __restrict__ Q, const float* __restrict__ Kg,
    const float* __restrict__ Vg, float* __restrict__ ctx)
{
    int b = blockIdx.z, h = blockIdx.y;
    int qrow = blockIdx.x * 128 + threadIdx.x;

    const float* qp = Q + ((size_t)(b * NHEAD + h) * SEQ + qrow) * HDIM;
    float q[HDIM];
#pragma unroll
    for (int i = 0; i < 16; i++)
        *(float4*)&q[i * 4] = *(const float4*)&qp[i * 4];

    float o[HDIM];
#pragma unroll
    for (int d = 0; d < HDIM; d++) o[d] = 0.f;
    float m = -1e30f, l = 0.f;

    int nearest = g_nearest[b * SEQ + qrow];
    const float* Kbase = Kg + (size_t)(b * NHEAD + h) * SEQ * HDIM;
    const float* Vbase = Vg + (size_t)(b * NHEAD + h) * SEQ * HDIM;

    __shared__ float Ks[32][64];
    __shared__ float Vs[32][64];
    __shared__ float cb[32];

    for (int kt = 0; kt < SEQ; kt += 32) {
        __syncthreads();
#pragma unroll
        for (int r = 0; r < 4; r++) {
            int f4 = threadIdx.x + r * 128;          // 0..511 float4 slots
            int row = f4 >> 4, col = (f4 & 15) * 4;
            *(float4*)&Ks[row][col] = *(const float4*)&Kbase[(size_t)(kt + row) * HDIM + col];
            *(float4*)&Vs[row][col] = *(const float4*)&Vbase[(size_t)(kt + row) * HDIM + col];
        }
        if (threadIdx.x < 32) cb[threadIdx.x] = g_colbias[b * SEQ + kt + threadIdx.x];
        __syncthreads();

        float s[32];
#pragma unroll
        for (int j = 0; j < 32; j++) {
            float acc = 0.f;
#pragma unroll
            for (int dv = 0; dv < 16; dv++) {
                float4 kk = *(const float4*)&Ks[j][dv * 4];
                acc += q[dv*4+0]*kk.x + q[dv*4+1]*kk.y + q[dv*4+2]*kk.z + q[dv*4+3]*kk.w;
            }
            int jg = kt + j;
            s[j] = acc * SCALE + cb[j] + (jg == nearest ? 2.0f : 0.0f);
        }

        float mt = s[0];
#pragma unroll
        for (int j = 1; j < 32; j++) mt = fmaxf(mt, s[j]);
        float newm = fmaxf(m, mt);
        float corr = __expf(m - newm);
        l *= corr;
#pragma unroll
        for (int d = 0; d < HDIM; d++) o[d] *= corr;

#pragma unroll
        for (int j = 0; j < 32; j++) {
            float p = __expf(s[j] - newm);
            l += p;
#pragma unroll
            for (int dv = 0; dv < 16; dv++) {
                float4 vv = *(const float4*)&Vs[j][dv * 4];
                o[dv*4+0] += p * vv.x; o[dv*4+1] += p * vv.y;
                o[dv*4+2] += p * vv.z; o[dv*4+3] += p * vv.w;
            }
        }
        m = newm;
    }

    float inv = 1.f / l;
    float* op = ctx + ((size_t)(b * SEQ + qrow)) * HID + h * HDIM;
#pragma unroll
    for (int i = 0; i < 16; i++) {
        float4 v;
        v.x = o[i*4+0] * inv; v.y = o[i*4+1] * inv;
        v.z = o[i*4+2] * inv; v.w = o[i*4+3] * inv;
        *(float4*)&op[i * 4] = v;
    }
}

// ---------------------------------------------------------------------------
extern "C" void kernel_launch(void* const* d_in, const int* in_sizes, int n_in,
                              void* d_out, int out_size)
{
    const float* hs     = (const float*)d_in[0];
    const int*   morpho = (const int*)  d_in[1];
    const float* Wq = (const float*)d_in[2];
    const float* bq = (const float*)d_in[3];
    const float* Wk = (const float*)d_in[4];
    const float* bk = (const float*)d_in[5];
    const float* Wv = (const float*)d_in[6];
    const float* bv = (const float*)d_in[7];
    const float* Wo = (const float*)d_in[8];
    const float* bo = (const float*)d_in[9];
    float* out = (float*)d_out;

    float *qp, *kp, *vp, *cp;
    cudaGetSymbolAddress((void**)&qp, g_Q);
    cudaGetSymbolAddress((void**)&kp, g_K);
    cudaGetSymbolAddress((void**)&vp, g_V);
    cudaGetSymbolAddress((void**)&cp, g_ctx);

    bias_kernel<<<BATCH, 256>>>(morpho);

    dim3 gg(HID / 128, (BATCH * SEQ) / 128);   // 8 x 32 blocks
    gemm128<<<gg, 256>>>(hs, Wq, bq, qp, 0);
    gemm128<<<gg, 256>>>(hs, Wk, bk, kp, 0);
    gemm128<<<gg, 256>>>(hs, Wv, bv, vp, 0);

    attn_kernel<<<dim3(SEQ / 128, NHEAD, BATCH), 128>>>(qp, kp, vp, cp);

    gemm128<<<gg, 256>>>(cp, Wo, bo, out, 1);
}

// round 5
// speedup vs baseline: 1.6856x; 1.6856x over previous
#include <cuda_runtime.h>
#include <cuda_bf16.h>
#include <cstdint>
#include <math.h>

#define BATCH 4
#define SEQ   1024
#define HID   1024
#define NHEAD 16
#define HDIM  64
#define SCALE 0.125f
#define MTOT  (BATCH*SEQ)

// ------------------------- scratch (device globals) -------------------------
__device__ __nv_bfloat16 g_Ahi[MTOT*HID];        // hi/lo split of GEMM A input
__device__ __nv_bfloat16 g_Alo[MTOT*HID];
__device__ __nv_bfloat16 g_Whi[4*HID*HID];       // transposed weights [N][K], 4 slots
__device__ __nv_bfloat16 g_Wlo[4*HID*HID];
__device__ float g_Q[MTOT*HID];                  // row-major [b*S+s][h*64+d]
__device__ float g_K[MTOT*HID];
__device__ float g_V[MTOT*HID];
__device__ float g_ctx[MTOT*HID];
__device__ int   g_nearest[BATCH*SEQ];
__device__ float g_colbias[BATCH*SEQ];

// ------------------------------ PTX helpers ---------------------------------
__device__ __forceinline__ uint32_t smem_u32(const void* p) {
    uint32_t a;
    asm("{ .reg .u64 t; cvta.to.shared.u64 t, %1; cvt.u32.u64 %0, t; }"
        : "=r"(a) : "l"(p));
    return a;
}

__device__ __forceinline__ void cp_async16(uint32_t saddr, const void* gaddr) {
    asm volatile("cp.async.cg.shared.global [%0], [%1], 16;"
                 :: "r"(saddr), "l"(gaddr) : "memory");
}

__device__ __forceinline__ void ldmatrix_x4(uint32_t* r, uint32_t addr) {
    asm volatile("ldmatrix.sync.aligned.m8n8.x4.shared.b16 {%0,%1,%2,%3}, [%4];"
                 : "=r"(r[0]), "=r"(r[1]), "=r"(r[2]), "=r"(r[3]) : "r"(addr));
}

__device__ __forceinline__ void mma16816(float* d, const uint32_t* a,
                                         uint32_t b0, uint32_t b1) {
    asm volatile(
        "mma.sync.aligned.m16n8k16.row.col.f32.bf16.bf16.f32 "
        "{%0,%1,%2,%3}, {%4,%5,%6,%7}, {%8,%9}, {%0,%1,%2,%3};"
        : "+f"(d[0]), "+f"(d[1]), "+f"(d[2]), "+f"(d[3])
        : "r"(a[0]), "r"(a[1]), "r"(a[2]), "r"(a[3]), "r"(b0), "r"(b1));
}

#define SWZ(x) ((x) ^ (((x) >> 3) & 0x70))

// ---------------------------------------------------------------------------
// Morphological bias precompute
// ---------------------------------------------------------------------------
__global__ void bias_kernel(const int* __restrict__ morpho)
{
    int b = blockIdx.x;
    __shared__ int types[SEQ];
    for (int i = threadIdx.x; i < SEQ; i += blockDim.x)
        types[i] = morpho[b*SEQ + i];
    __syncthreads();
    for (int q = threadIdx.x; q < SEQ; q += blockDim.x) {
        int best = -1;
        int bestd = 1 << 30;
        for (int j = 0; j < SEQ; j++) {
            if (types[j] == 2) {
                int d = abs(q - j);
                if (d < bestd) { bestd = d; best = j; }
            }
        }
        g_nearest[b*SEQ + q] = best;
        int t = types[q];
        float cb = 0.0f;
        if (t == 0) cb = 0.75f;
        else if (t == 1) cb = 0.36f;
        g_colbias[b*SEQ + q] = cb;
    }
}

// ---------------------------------------------------------------------------
// fp32 -> bf16 hi/lo split (row-major, vectorized by 4)
// ---------------------------------------------------------------------------
__global__ void __launch_bounds__(256) split_kernel(
    const float4* __restrict__ src, __nv_bfloat162* __restrict__ hi,
    __nv_bfloat162* __restrict__ lo)
{
    int i = blockIdx.x * 256 + threadIdx.x;
    float4 v = src[i];
    __nv_bfloat16 h0 = __float2bfloat16(v.x);
    __nv_bfloat16 h1 = __float2bfloat16(v.y);
    __nv_bfloat16 h2 = __float2bfloat16(v.z);
    __nv_bfloat16 h3 = __float2bfloat16(v.w);
    __nv_bfloat162 ha; ha.x = h0; ha.y = h1;
    __nv_bfloat162 hb; hb.x = h2; hb.y = h3;
    hi[2*i] = ha; hi[2*i+1] = hb;
    __nv_bfloat162 la, lb;
    la.x = __float2bfloat16(v.x - __bfloat162float(h0));
    la.y = __float2bfloat16(v.y - __bfloat162float(h1));
    lb.x = __float2bfloat16(v.z - __bfloat162float(h2));
    lb.y = __float2bfloat16(v.w - __bfloat162float(h3));
    lo[2*i] = la; lo[2*i+1] = lb;
}

// ---------------------------------------------------------------------------
// W [K][N] fp32 -> Wt hi/lo [N][K] bf16 (transpose + split)
// ---------------------------------------------------------------------------
__global__ void wtrans_kernel(const float* __restrict__ W,
                              __nv_bfloat16* __restrict__ hi,
                              __nv_bfloat16* __restrict__ lo)
{
    __shared__ float t[32][33];
    int n0 = blockIdx.x * 32, k0 = blockIdx.y * 32;
    int c = threadIdx.x, r0 = threadIdx.y;        // 32 x 8
#pragma unroll
    for (int i = 0; i < 4; i++)
        t[r0 + 8*i][c] = W[(size_t)(k0 + r0 + 8*i) * HID + n0 + c];
    __syncthreads();
#pragma unroll
    for (int i = 0; i < 4; i++) {
        int rr = r0 + 8*i;
        float v = t[c][rr];                       // = W[k0+c][n0+rr]
        __nv_bfloat16 h = __float2bfloat16(v);
        hi[(size_t)(n0 + rr) * HID + k0 + c] = h;
        lo[(size_t)(n0 + rr) * HID + k0 + c] =
            __float2bfloat16(v - __bfloat162float(h));
    }
}

// ---------------------------------------------------------------------------
// mma.sync bf16-split GEMM: C[M,1024] = A @ Wt^T + bias, fp32-class accuracy.
// D = Ah*Bh + Ah*Bl + Al*Bh  (3 passes over K, accumulated in registers).
// CTA 128x128, 8 warps (2x4), warp tile 64x32. K chunk 64, double-buffered
// cp.async, SW128-swizzled smem, ldmatrix feeds.
// ---------------------------------------------------------------------------
__global__ void __launch_bounds__(256) gemm_mma(
    const __nv_bfloat16* __restrict__ Ahi, const __nv_bfloat16* __restrict__ Alo,
    const __nv_bfloat16* __restrict__ Bhi, const __nv_bfloat16* __restrict__ Blo,
    const float* __restrict__ bias, float* __restrict__ C)
{
    extern __shared__ __align__(1024) char smem[];
    // layout: A buf0 [0,16K) A buf1 [16K,32K) B buf0 [32K,48K) B buf1 [48K,64K)

    const int tid = threadIdx.x;
    const int L = tid & 31;
    const int wid = tid >> 5;
    const int wm = wid >> 2;            // 0..1  -> rows wm*64
    const int wn = wid & 3;             // 0..3  -> cols wn*32
    const int bm = blockIdx.y * 128, bn = blockIdx.x * 128;

    const uint32_t sbase = smem_u32(smem);

    // per-thread global load coords: 8 x 16B units per buffer half (A and B)
    const int ldrow = tid >> 1;               // 0..127
    const int ldcu  = (tid & 1) * 4;          // 16B-unit col 0..7 (covers 4 each)

    float acc[4][4][4];
#pragma unroll
    for (int i = 0; i < 4; i++)
#pragma unroll
        for (int j = 0; j < 4; j++)
#pragma unroll
            for (int k = 0; k < 4; k++) acc[i][j][k] = 0.f;

    // ldmatrix base addresses (byte offsets inside a 16KB tile)
    // A frags: row = wm*64 + mt*16 + (L&15), colbyte = ks*32 + (L>>4)*16
    uint32_t aRow = (uint32_t)(wm * 64 + (L & 15)) * 128 + ((L >> 4) << 4);
    // B frags: n = wn*32 + p*16 + (L&7) + ((L>>4)&1)*8, kbyte = ks*32 + ((L>>3)&1)*16
    uint32_t bRow = (uint32_t)(wn * 32 + (L & 7) + ((L >> 4) & 1) * 8) * 128
                  + (((L >> 3) & 1) << 4);

    auto loadChunk = [&](int it) {
        int pass = it >> 4;
        int k0 = (it & 15) << 6;
        int buf = it & 1;
        const __nv_bfloat16* Ap = (pass == 2) ? Alo : Ahi;
        const __nv_bfloat16* Bp = (pass == 1) ? Blo : Bhi;
        uint32_t sa = sbase + buf * 16384;
        uint32_t sb = sbase + 32768 + buf * 16384;
#pragma unroll
        for (int i = 0; i < 4; i++) {
            uint32_t off = (uint32_t)(ldrow * 128) + ((ldcu + i) << 4);
            uint32_t sw = SWZ(off);
            cp_async16(sa + sw, Ap + (size_t)(bm + ldrow) * HID + k0 + ((ldcu + i) << 3));
            cp_async16(sb + sw, Bp + (size_t)(bn + ldrow) * HID + k0 + ((ldcu + i) << 3));
        }
    };

    loadChunk(0);
    asm volatile("cp.async.commit_group;" ::: "memory");

    for (int it = 0; it < 48; it++) {
        asm volatile("cp.async.wait_group 0;" ::: "memory");
        __syncthreads();
        if (it + 1 < 48) {
            loadChunk(it + 1);
            asm volatile("cp.async.commit_group;" ::: "memory");
        }

        int buf = it & 1;
        uint32_t sa = sbase + buf * 16384;
        uint32_t sb = sbase + 32768 + buf * 16384;

#pragma unroll
        for (int ks = 0; ks < 4; ks++) {
            uint32_t a[4][4], b[2][4];
#pragma unroll
            for (int mt = 0; mt < 4; mt++) {
                uint32_t off = aRow + (uint32_t)(mt * 16 * 128) + (uint32_t)(ks * 32);
                ldmatrix_x4(a[mt], sa + SWZ(off));
            }
#pragma unroll
            for (int p = 0; p < 2; p++) {
                uint32_t off = bRow + (uint32_t)(p * 16 * 128) + (uint32_t)(ks * 32);
                ldmatrix_x4(b[p], sb + SWZ(off));
            }
#pragma unroll
            for (int mt = 0; mt < 4; mt++)
#pragma unroll
                for (int nt = 0; nt < 4; nt++)
                    mma16816(acc[mt][nt], a[mt],
                             b[nt >> 1][(nt & 1) * 2], b[nt >> 1][(nt & 1) * 2 + 1]);
        }
    }

    // epilogue: registers -> global with bias
    const int r = L >> 2, c2 = (L & 3) * 2;
#pragma unroll
    for (int mt = 0; mt < 4; mt++) {
        int gm0 = bm + wm * 64 + mt * 16 + r;
#pragma unroll
        for (int nt = 0; nt < 4; nt++) {
            int gn = bn + wn * 32 + nt * 8 + c2;
            float b0 = bias[gn], b1 = bias[gn + 1];
            float2 v0, v1;
            v0.x = acc[mt][nt][0] + b0; v0.y = acc[mt][nt][1] + b1;
            v1.x = acc[mt][nt][2] + b0; v1.y = acc[mt][nt][3] + b1;
            *(float2*)(C + (size_t)gm0 * HID + gn) = v0;
            *(float2*)(C + (size_t)(gm0 + 8) * HID + gn) = v1;
        }
    }
}

// ---------------------------------------------------------------------------
// Flash-style attention, fp32. Q/K/V row-major [b*S+s][h*64+d] (stride 1024).
// ---------------------------------------------------------------------------
__global__ void __launch_bounds__(128) attn_kernel(
    const float* __restrict__ Q, const float* __restrict__ Kg,
    const float* __restrict__ Vg, float* __restrict__ ctx)
{
    int b = blockIdx.z, h = blockIdx.y;
    int qrow = blockIdx.x * 128 + threadIdx.x;

    const float* qp = Q + ((size_t)(b * SEQ + qrow)) * HID + h * HDIM;
    float q[HDIM];
#pragma unroll
    for (int i = 0; i < 16; i++)
        *(float4*)&q[i * 4] = *(const float4*)&qp[i * 4];

    float o[HDIM];
#pragma unroll
    for (int d = 0; d < HDIM; d++) o[d] = 0.f;
    float m = -1e30f, l = 0.f;

    int nearest = g_nearest[b * SEQ + qrow];
    const float* Kbase = Kg + ((size_t)(b * SEQ)) * HID + h * HDIM;
    const float* Vbase = Vg + ((size_t)(b * SEQ)) * HID + h * HDIM;

    __shared__ float Ks[32][64];
    __shared__ float Vs[32][64];
    __shared__ float cb[32];

    for (int kt = 0; kt < SEQ; kt += 32) {
        __syncthreads();
#pragma unroll
        for (int r = 0; r < 4; r++) {
            int f4 = threadIdx.x + r * 128;
            int row = f4 >> 4, col = (f4 & 15) * 4;
            *(float4*)&Ks[row][col] = *(const float4*)&Kbase[(size_t)(kt + row) * HID + col];
            *(float4*)&Vs[row][col] = *(const float4*)&Vbase[(size_t)(kt + row) * HID + col];
        }
        if (threadIdx.x < 32) cb[threadIdx.x] = g_colbias[b * SEQ + kt + threadIdx.x];
        __syncthreads();

        float s[32];
#pragma unroll
        for (int j = 0; j < 32; j++) {
            float acc = 0.f;
#pragma unroll
            for (int dv = 0; dv < 16; dv++) {
                float4 kk = *(const float4*)&Ks[j][dv * 4];
                acc += q[dv*4+0]*kk.x + q[dv*4+1]*kk.y + q[dv*4+2]*kk.z + q[dv*4+3]*kk.w;
            }
            int jg = kt + j;
            s[j] = acc * SCALE + cb[j] + (jg == nearest ? 2.0f : 0.0f);
        }

        float mt = s[0];
#pragma unroll
        for (int j = 1; j < 32; j++) mt = fmaxf(mt, s[j]);
        float newm = fmaxf(m, mt);
        float corr = __expf(m - newm);
        l *= corr;
#pragma unroll
        for (int d = 0; d < HDIM; d++) o[d] *= corr;

#pragma unroll
        for (int j = 0; j < 32; j++) {
            float p = __expf(s[j] - newm);
            l += p;
#pragma unroll
            for (int dv = 0; dv < 16; dv++) {
                float4 vv = *(const float4*)&Vs[j][dv * 4];
                o[dv*4+0] += p * vv.x; o[dv*4+1] += p * vv.y;
                o[dv*4+2] += p * vv.z; o[dv*4+3] += p * vv.w;
            }
        }
        m = newm;
    }

    float inv = 1.f / l;
    float* op = ctx + ((size_t)(b * SEQ + qrow)) * HID + h * HDIM;
#pragma unroll
    for (int i = 0; i < 16; i++) {
        float4 v;
        v.x = o[i*4+0] * inv; v.y = o[i*4+1] * inv;
        v.z = o[i*4+2] * inv; v.w = o[i*4+3] * inv;
        *(float4*)&op[i * 4] = v;
    }
}

// ---------------------------------------------------------------------------
extern "C" void kernel_launch(void* const* d_in, const int* in_sizes, int n_in,
                              void* d_out, int out_size)
{
    const float* hs     = (const float*)d_in[0];
    const int*   morpho = (const int*)  d_in[1];
    const float* Wq = (const float*)d_in[2];
    const float* bq = (const float*)d_in[3];
    const float* Wk = (const float*)d_in[4];
    const float* bk = (const float*)d_in[5];
    const float* Wv = (const float*)d_in[6];
    const float* bv = (const float*)d_in[7];
    const float* Wo = (const float*)d_in[8];
    const float* bo = (const float*)d_in[9];
    float* out = (float*)d_out;

    __nv_bfloat16 *ahi, *alo, *whi, *wlo;
    float *qp, *kp, *vp, *cp;
    cudaGetSymbolAddress((void**)&ahi, g_Ahi);
    cudaGetSymbolAddress((void**)&alo, g_Alo);
    cudaGetSymbolAddress((void**)&whi, g_Whi);
    cudaGetSymbolAddress((void**)&wlo, g_Wlo);
    cudaGetSymbolAddress((void**)&qp, g_Q);
    cudaGetSymbolAddress((void**)&kp, g_K);
    cudaGetSymbolAddress((void**)&vp, g_V);
    cudaGetSymbolAddress((void**)&cp, g_ctx);

    static bool attr_set = false;
    if (!attr_set) {
        cudaFuncSetAttribute(gemm_mma,
                             cudaFuncAttributeMaxDynamicSharedMemorySize, 65536);
        attr_set = true;
    }

    bias_kernel<<<BATCH, 256>>>(morpho);

    // hi/lo split of hidden_states
    split_kernel<<<MTOT*HID/1024, 256>>>((const float4*)hs,
                                         (__nv_bfloat162*)ahi, (__nv_bfloat162*)alo);

    // weight transposes + splits (4 slots)
    dim3 wtg(HID/32, HID/32), wtb(32, 8);
    wtrans_kernel<<<wtg, wtb>>>(Wq, whi + 0*HID*HID, wlo + 0*HID*HID);
    wtrans_kernel<<<wtg, wtb>>>(Wk, whi + 1*HID*HID, wlo + 1*HID*HID);
    wtrans_kernel<<<wtg, wtb>>>(Wv, whi + 2*HID*HID, wlo + 2*HID*HID);
    wtrans_kernel<<<wtg, wtb>>>(Wo, whi + 3*HID*HID, wlo + 3*HID*HID);

    dim3 gg(HID/128, MTOT/128);   // 8 x 32
    gemm_mma<<<gg, 256, 65536>>>(ahi, alo, whi + 0*HID*HID, wlo + 0*HID*HID, bq, qp);
    gemm_mma<<<gg, 256, 65536>>>(ahi, alo, whi + 1*HID*HID, wlo + 1*HID*HID, bk, kp);
    gemm_mma<<<gg, 256, 65536>>>(ahi, alo, whi + 2*HID*HID, wlo + 2*HID*HID, bv, vp);

    attn_kernel<<<dim3(SEQ/128, NHEAD, BATCH), 128>>>(qp, kp, vp, cp);

    // split context, final projection
    split_kernel<<<MTOT*HID/1024, 256>>>((const float4*)cp,
                                         (__nv_bfloat162*)ahi, (__nv_bfloat162*)alo);
    gemm_mma<<<gg, 256, 65536>>>(ahi, alo, whi + 3*HID*HID, wlo + 3*HID*HID, bo, out);
}

// round 7
// speedup vs baseline: 1.8644x; 1.1061x over previous
#include <cuda_runtime.h>
#include <cuda_bf16.h>
#include <cstdint>
#include <math.h>

#define BATCH 4
#define SEQ   1024
#define HID   1024
#define NHEAD 16
#define HDIM  64
#define SCALE 0.125f
#define MTOT  (BATCH*SEQ)

// ------------------------- scratch (device globals) -------------------------
__device__ __nv_bfloat16 g_Ahi[MTOT*HID];        // hi/lo split of GEMM A input
__device__ __nv_bfloat16 g_Alo[MTOT*HID];
__device__ __nv_bfloat16 g_Whi[4*HID*HID];       // transposed weights [N][K], 4 slots
__device__ __nv_bfloat16 g_Wlo[4*HID*HID];
// Q/K/V bf16 hi/lo, head-major [b][h][s][d]
__device__ __nv_bfloat16 g_Qhi[MTOT*HID];
__device__ __nv_bfloat16 g_Qlo[MTOT*HID];
__device__ __nv_bfloat16 g_Khi[MTOT*HID];
__device__ __nv_bfloat16 g_Klo[MTOT*HID];
__device__ __nv_bfloat16 g_Vhi[MTOT*HID];
__device__ __nv_bfloat16 g_Vlo[MTOT*HID];
__device__ int   g_nearest[BATCH*SEQ];
__device__ float g_colbias[BATCH*SEQ];

// ------------------------------ PTX helpers ---------------------------------
__device__ __forceinline__ uint32_t smem_u32(const void* p) {
    uint32_t a;
    asm("{ .reg .u64 t; cvta.to.shared.u64 t, %1; cvt.u32.u64 %0, t; }"
        : "=r"(a) : "l"(p));
    return a;
}

__device__ __forceinline__ void cp_async16(uint32_t saddr, const void* gaddr) {
    asm volatile("cp.async.cg.shared.global [%0], [%1], 16;"
                 :: "r"(saddr), "l"(gaddr) : "memory");
}

__device__ __forceinline__ void ldmatrix_x4(uint32_t* r, uint32_t addr) {
    asm volatile("ldmatrix.sync.aligned.m8n8.x4.shared.b16 {%0,%1,%2,%3}, [%4];"
                 : "=r"(r[0]), "=r"(r[1]), "=r"(r[2]), "=r"(r[3]) : "r"(addr));
}

__device__ __forceinline__ void ldmatrix_x4_t(uint32_t* r, uint32_t addr) {
    asm volatile("ldmatrix.sync.aligned.m8n8.x4.trans.shared.b16 {%0,%1,%2,%3}, [%4];"
                 : "=r"(r[0]), "=r"(r[1]), "=r"(r[2]), "=r"(r[3]) : "r"(addr));
}

__device__ __forceinline__ void mma16816(float* d, const uint32_t* a,
                                         uint32_t b0, uint32_t b1) {
    asm volatile(
        "mma.sync.aligned.m16n8k16.row.col.f32.bf16.bf16.f32 "
        "{%0,%1,%2,%3}, {%4,%5,%6,%7}, {%8,%9}, {%0,%1,%2,%3};"
        : "+f"(d[0]), "+f"(d[1]), "+f"(d[2]), "+f"(d[3])
        : "r"(a[0]), "r"(a[1]), "r"(a[2]), "r"(a[3]), "r"(b0), "r"(b1));
}

#define SWZ(x) ((x) ^ (((x) >> 3) & 0x70))

__device__ __forceinline__ uint32_t pack_bf2(float x, float y) {
    __nv_bfloat162 h = __floats2bfloat162_rn(x, y);   // .x=x (low), .y=y (high)
    return *(uint32_t*)&h;
}

// ---------------------------------------------------------------------------
// Morphological bias precompute
// ---------------------------------------------------------------------------
__global__ void bias_kernel(const int* __restrict__ morpho)
{
    int b = blockIdx.x;
    __shared__ int types[SEQ];
    for (int i = threadIdx.x; i < SEQ; i += blockDim.x)
        types[i] = morpho[b*SEQ + i];
    __syncthreads();
    for (int q = threadIdx.x; q < SEQ; q += blockDim.x) {
        int best = -1;
        int bestd = 1 << 30;
        for (int j = 0; j < SEQ; j++) {
            if (types[j] == 2) {
                int d = abs(q - j);
                if (d < bestd) { bestd = d; best = j; }
            }
        }
        g_nearest[b*SEQ + q] = best;
        int t = types[q];
        float cb = 0.0f;
        if (t == 0) cb = 0.75f;
        else if (t == 1) cb = 0.36f;
        g_colbias[b*SEQ + q] = cb;
    }
}

// ---------------------------------------------------------------------------
// fp32 -> bf16 hi/lo split (row-major, vectorized by 4)
// ---------------------------------------------------------------------------
__global__ void __launch_bounds__(256) split_kernel(
    const float4* __restrict__ src, __nv_bfloat162* __restrict__ hi,
    __nv_bfloat162* __restrict__ lo)
{
    int i = blockIdx.x * 256 + threadIdx.x;
    float4 v = src[i];
    __nv_bfloat16 h0 = __float2bfloat16(v.x);
    __nv_bfloat16 h1 = __float2bfloat16(v.y);
    __nv_bfloat16 h2 = __float2bfloat16(v.z);
    __nv_bfloat16 h3 = __float2bfloat16(v.w);
    __nv_bfloat162 ha; ha.x = h0; ha.y = h1;
    __nv_bfloat162 hb; hb.x = h2; hb.y = h3;
    hi[2*i] = ha; hi[2*i+1] = hb;
    __nv_bfloat162 la, lb;
    la.x = __float2bfloat16(v.x - __bfloat162float(h0));
    la.y = __float2bfloat16(v.y - __bfloat162float(h1));
    lb.x = __float2bfloat16(v.z - __bfloat162float(h2));
    lb.y = __float2bfloat16(v.w - __bfloat162float(h3));
    lo[2*i] = la; lo[2*i+1] = lb;
}

// ---------------------------------------------------------------------------
// W [K][N] fp32 -> Wt hi/lo [N][K] bf16 (transpose + split)
// ---------------------------------------------------------------------------
__global__ void wtrans_kernel(const float* __restrict__ W,
                              __nv_bfloat16* __restrict__ hi,
                              __nv_bfloat16* __restrict__ lo)
{
    __shared__ float t[32][33];
    int n0 = blockIdx.x * 32, k0 = blockIdx.y * 32;
    int c = threadIdx.x, r0 = threadIdx.y;        // 32 x 8
#pragma unroll
    for (int i = 0; i < 4; i++)
        t[r0 + 8*i][c] = W[(size_t)(k0 + r0 + 8*i) * HID + n0 + c];
    __syncthreads();
#pragma unroll
    for (int i = 0; i < 4; i++) {
        int rr = r0 + 8*i;
        float v = t[c][rr];
        __nv_bfloat16 h = __float2bfloat16(v);
        hi[(size_t)(n0 + rr) * HID + k0 + c] = h;
        lo[(size_t)(n0 + rr) * HID + k0 + c] =
            __float2bfloat16(v - __bfloat162float(h));
    }
}

// ---------------------------------------------------------------------------
// mma.sync bf16-split GEMM: C[M,1024] = A @ Wt^T + bias.
// mode 0: fp32 row-major out. mode 1: (acc+bias)*scale split to bf16 hi/lo,
// scattered head-major [b][h][s][d].
// ---------------------------------------------------------------------------
__global__ void __launch_bounds__(256) gemm_mma(
    const __nv_bfloat16* __restrict__ Ahi, const __nv_bfloat16* __restrict__ Alo,
    const __nv_bfloat16* __restrict__ Bhi, const __nv_bfloat16* __restrict__ Blo,
    const float* __restrict__ bias, float* __restrict__ C,
    __nv_bfloat16* __restrict__ Chi, __nv_bfloat16* __restrict__ Clo,
    float scale, int mode)
{
    extern __shared__ __align__(1024) char smem[];

    const int tid = threadIdx.x;
    const int L = tid & 31;
    const int wid = tid >> 5;
    const int wm = wid >> 2;
    const int wn = wid & 3;
    const int bm = blockIdx.y * 128, bn = blockIdx.x * 128;

    const uint32_t sbase = smem_u32(smem);

    const int ldrow = tid >> 1;
    const int ldcu  = (tid & 1) * 4;

    float acc[4][4][4];
#pragma unroll
    for (int i = 0; i < 4; i++)
#pragma unroll
        for (int j = 0; j < 4; j++)
#pragma unroll
            for (int k = 0; k < 4; k++) acc[i][j][k] = 0.f;

    uint32_t aRow = (uint32_t)(wm * 64 + (L & 15)) * 128 + ((L >> 4) << 4);
    uint32_t bRow = (uint32_t)(wn * 32 + (L & 7) + ((L >> 4) & 1) * 8) * 128
                  + (((L >> 3) & 1) << 4);

    auto loadChunk = [&](int it) {
        int pass = it >> 4;
        int k0 = (it & 15) << 6;
        int buf = it & 1;
        const __nv_bfloat16* Ap = (pass == 2) ? Alo : Ahi;
        const __nv_bfloat16* Bp = (pass == 1) ? Blo : Bhi;
        uint32_t sa = sbase + buf * 16384;
        uint32_t sb = sbase + 32768 + buf * 16384;
#pragma unroll
        for (int i = 0; i < 4; i++) {
            uint32_t off = (uint32_t)(ldrow * 128) + ((ldcu + i) << 4);
            uint32_t sw = SWZ(off);
            cp_async16(sa + sw, Ap + (size_t)(bm + ldrow) * HID + k0 + ((ldcu + i) << 3));
            cp_async16(sb + sw, Bp + (size_t)(bn + ldrow) * HID + k0 + ((ldcu + i) << 3));
        }
    };

    loadChunk(0);
    asm volatile("cp.async.commit_group;" ::: "memory");

    for (int it = 0; it < 48; it++) {
        asm volatile("cp.async.wait_group 0;" ::: "memory");
        __syncthreads();
        if (it + 1 < 48) {
            loadChunk(it + 1);
            asm volatile("cp.async.commit_group;" ::: "memory");
        }

        int buf = it & 1;
        uint32_t sa = sbase + buf * 16384;
        uint32_t sb = sbase + 32768 + buf * 16384;

#pragma unroll
        for (int ks = 0; ks < 4; ks++) {
            uint32_t a[4][4], b[2][4];
#pragma unroll
            for (int mt = 0; mt < 4; mt++) {
                uint32_t off = aRow + (uint32_t)(mt * 16 * 128) + (uint32_t)(ks * 32);
                ldmatrix_x4(a[mt], sa + SWZ(off));
            }
#pragma unroll
            for (int p = 0; p < 2; p++) {
                uint32_t off = bRow + (uint32_t)(p * 16 * 128) + (uint32_t)(ks * 32);
                ldmatrix_x4(b[p], sb + SWZ(off));
            }
#pragma unroll
            for (int mt = 0; mt < 4; mt++)
#pragma unroll
                for (int nt = 0; nt < 4; nt++)
                    mma16816(acc[mt][nt], a[mt],
                             b[nt >> 1][(nt & 1) * 2], b[nt >> 1][(nt & 1) * 2 + 1]);
        }
    }

    const int r = L >> 2, c2 = (L & 3) * 2;
#pragma unroll
    for (int mt = 0; mt < 4; mt++) {
        int gm0 = bm + wm * 64 + mt * 16 + r;
#pragma unroll
        for (int nt = 0; nt < 4; nt++) {
            int gn = bn + wn * 32 + nt * 8 + c2;
            float b0 = bias[gn], b1 = bias[gn + 1];
            float v00 = acc[mt][nt][0] + b0, v01 = acc[mt][nt][1] + b1;
            float v10 = acc[mt][nt][2] + b0, v11 = acc[mt][nt][3] + b1;
            if (mode == 0) {
                float2 w0; w0.x = v00; w0.y = v01;
                float2 w1; w1.x = v10; w1.y = v11;
                *(float2*)(C + (size_t)gm0 * HID + gn) = w0;
                *(float2*)(C + (size_t)(gm0 + 8) * HID + gn) = w1;
            } else {
                v00 *= scale; v01 *= scale; v10 *= scale; v11 *= scale;
                int hh = gn >> 6, d = gn & 63;
#pragma unroll
                for (int half = 0; half < 2; half++) {
                    int gm = gm0 + half * 8;
                    float x = half ? v10 : v00, y = half ? v11 : v01;
                    int bb = gm >> 10, s = gm & 1023;
                    size_t idx = ((size_t)((bb * NHEAD + hh) * SEQ) + s) * HDIM + d;
                    __nv_bfloat162 hp = __floats2bfloat162_rn(x, y);
                    float2 hf = __bfloat1622float2(hp);
                    __nv_bfloat162 lp = __floats2bfloat162_rn(x - hf.x, y - hf.y);
                    *(__nv_bfloat162*)(Chi + idx) = hp;
                    *(__nv_bfloat162*)(Clo + idx) = lp;
                }
            }
        }
    }
}

// ---------------------------------------------------------------------------
// Tensor-core flash attention, bf16-split (3-term) for QK^T and P.V.
// CTA = 128 q-rows x one (b,h); 8 warps, 16 rows/warp; KV tile = 64.
// Writes context directly as bf16 hi/lo into the final GEMM's A buffers.
// ---------------------------------------------------------------------------
__global__ void __launch_bounds__(256) attn_mma(
    const __nv_bfloat16* __restrict__ Qhi, const __nv_bfloat16* __restrict__ Qlo,
    const __nv_bfloat16* __restrict__ Khi, const __nv_bfloat16* __restrict__ Klo,
    const __nv_bfloat16* __restrict__ Vhi, const __nv_bfloat16* __restrict__ Vlo,
    __nv_bfloat16* __restrict__ Chi, __nv_bfloat16* __restrict__ Clo)
{
    extern __shared__ __align__(1024) char smem[];   // 32 KB
    __shared__ float sCB[64];

    const int tid = threadIdx.x, L = tid & 31, wid = tid >> 5;
    const int b = blockIdx.z, h = blockIdx.y;
    const int qcta = blockIdx.x * 128;
    const int q0w = qcta + wid * 16;
    const uint32_t sb = smem_u32(smem);
    const size_t headbase = ((size_t)(b * NHEAD + h)) * SEQ;

    // ---- stage Q tile (128x64 hi+lo) through smem into A-fragments ----
    {
        const __nv_bfloat16* qh = Qhi + (headbase + qcta) * HDIM;
        const __nv_bfloat16* ql = Qlo + (headbase + qcta) * HDIM;
#pragma unroll
        for (int i = 0; i < 4; i++) {
            int u = tid + i * 256;
            int row = u >> 3, cu = u & 7;
            uint32_t sw = SWZ((uint32_t)(row * 128 + cu * 16));
            cp_async16(sb + sw, qh + (size_t)row * HDIM + cu * 8);
            cp_async16(sb + 16384 + sw, ql + (size_t)row * HDIM + cu * 8);
        }
        asm volatile("cp.async.commit_group;" ::: "memory");
        asm volatile("cp.async.wait_group 0;" ::: "memory");
        __syncthreads();
    }
    uint32_t qh[4][4], ql[4][4];
    {
        uint32_t base = (uint32_t)((wid * 16 + (L & 15)) * 128 + ((L >> 4) << 4));
#pragma unroll
        for (int ks = 0; ks < 4; ks++) {
            uint32_t off = SWZ(base + ks * 32);
            ldmatrix_x4(qh[ks], sb + off);
            ldmatrix_x4(ql[ks], sb + 16384 + off);
        }
    }

    const int nr0 = g_nearest[b * SEQ + q0w + (L >> 2)];
    const int nr1 = g_nearest[b * SEQ + q0w + (L >> 2) + 8];

    float o[8][4];
#pragma unroll
    for (int i = 0; i < 8; i++)
#pragma unroll
        for (int j = 0; j < 4; j++) o[i][j] = 0.f;
    float m0 = -1e30f, m1 = -1e30f, l0 = 0.f, l1 = 0.f;

    // B-operand (K) address base: n = kv row, k = d
    uint32_t kBase = (uint32_t)((L & 7) + ((L >> 4) & 1) * 8) * 128
                   + (((L >> 3) & 1) << 4);
    // B-operand (V, trans) address base: rows = kv, cols = d
    uint32_t vBase = (uint32_t)((L & 7) + ((L >> 3) & 1) * 8) * 128
                   + ((L >> 4) << 4);

    for (int kt = 0; kt < SEQ; kt += 64) {
        __syncthreads();
        {
            const __nv_bfloat16* kh = Khi + (headbase + kt) * HDIM;
            const __nv_bfloat16* kl = Klo + (headbase + kt) * HDIM;
            const __nv_bfloat16* vh = Vhi + (headbase + kt) * HDIM;
            const __nv_bfloat16* vl = Vlo + (headbase + kt) * HDIM;
#pragma unroll
            for (int i = 0; i < 2; i++) {
                int u = tid + i * 256;
                int row = u >> 3, cu = u & 7;
                uint32_t sw = SWZ((uint32_t)(row * 128 + cu * 16));
                size_t g = (size_t)row * HDIM + cu * 8;
                cp_async16(sb + sw,         kh + g);
                cp_async16(sb +  8192 + sw, kl + g);
                cp_async16(sb + 16384 + sw, vh + g);
                cp_async16(sb + 24576 + sw, vl + g);
            }
            if (tid < 64) sCB[tid] = g_colbias[b * SEQ + kt + tid];
            asm volatile("cp.async.commit_group;" ::: "memory");
            asm volatile("cp.async.wait_group 0;" ::: "memory");
            __syncthreads();
        }

        // ---- S = Qh*Kh + Qh*Kl + Ql*Kh ----
        float s[8][4];
#pragma unroll
        for (int i = 0; i < 8; i++)
#pragma unroll
            for (int j = 0; j < 4; j++) s[i][j] = 0.f;

#pragma unroll
        for (int ks = 0; ks < 4; ks++) {
#pragma unroll
            for (int p = 0; p < 4; p++) {
                uint32_t off = SWZ(kBase + (uint32_t)(p * 16 * 128) + (uint32_t)(ks * 32));
                uint32_t f[4];
                ldmatrix_x4(f, sb + off);                 // K hi
                mma16816(s[2*p],   qh[ks], f[0], f[1]);
                mma16816(s[2*p],   ql[ks], f[0], f[1]);
                mma16816(s[2*p+1], qh[ks], f[2], f[3]);
                mma16816(s[2*p+1], ql[ks], f[2], f[3]);
                ldmatrix_x4(f, sb + 8192 + off);          // K lo
                mma16816(s[2*p],   qh[ks], f[0], f[1]);
                mma16816(s[2*p+1], qh[ks], f[2], f[3]);
            }
        }

        // ---- bias + online softmax ----
        int colb = kt + 2 * (L & 3);
        float t0 = -1e30f, t1 = -1e30f;
#pragma unroll
        for (int nb = 0; nb < 8; nb++) {
            float c0 = sCB[nb * 8 + 2 * (L & 3)];
            float c1 = sCB[nb * 8 + 2 * (L & 3) + 1];
            int g0 = colb + nb * 8, g1 = g0 + 1;
            s[nb][0] += c0 + (g0 == nr0 ? 2.f : 0.f);
            s[nb][1] += c1 + (g1 == nr0 ? 2.f : 0.f);
            s[nb][2] += c0 + (g0 == nr1 ? 2.f : 0.f);
            s[nb][3] += c1 + (g1 == nr1 ? 2.f : 0.f);
            t0 = fmaxf(t0, fmaxf(s[nb][0], s[nb][1]));
            t1 = fmaxf(t1, fmaxf(s[nb][2], s[nb][3]));
        }
        t0 = fmaxf(t0, __shfl_xor_sync(0xffffffffu, t0, 1));
        t0 = fmaxf(t0, __shfl_xor_sync(0xffffffffu, t0, 2));
        t1 = fmaxf(t1, __shfl_xor_sync(0xffffffffu, t1, 1));
        t1 = fmaxf(t1, __shfl_xor_sync(0xffffffffu, t1, 2));
        float nm0 = fmaxf(m0, t0), nm1 = fmaxf(m1, t1);
        float cr0 = __expf(m0 - nm0), cr1 = __expf(m1 - nm1);
        m0 = nm0; m1 = nm1;
        l0 *= cr0; l1 *= cr1;
#pragma unroll
        for (int nb = 0; nb < 8; nb++) {
            o[nb][0] *= cr0; o[nb][1] *= cr0;
            o[nb][2] *= cr1; o[nb][3] *= cr1;
            s[nb][0] = __expf(s[nb][0] - m0); l0 += s[nb][0];
            s[nb][1] = __expf(s[nb][1] - m0); l0 += s[nb][1];
            s[nb][2] = __expf(s[nb][2] - m1); l1 += s[nb][2];
            s[nb][3] = __expf(s[nb][3] - m1); l1 += s[nb][3];
        }

        // ---- O += Ph*Vh + Ph*Vl + Pl*Vh ----
#pragma unroll
        for (int ks = 0; ks < 4; ks++) {
            uint32_t ah[4], al[4];
#pragma unroll
            for (int half = 0; half < 2; half++) {
                int nb = 2 * ks + half;
                __nv_bfloat162 h01 = __floats2bfloat162_rn(s[nb][0], s[nb][1]);
                __nv_bfloat162 h23 = __floats2bfloat162_rn(s[nb][2], s[nb][3]);
                float2 f01 = __bfloat1622float2(h01);
                float2 f23 = __bfloat1622float2(h23);
                ah[2*half]   = *(uint32_t*)&h01;
                ah[2*half+1] = *(uint32_t*)&h23;
                al[2*half]   = pack_bf2(s[nb][0] - f01.x, s[nb][1] - f01.y);
                al[2*half+1] = pack_bf2(s[nb][2] - f23.x, s[nb][3] - f23.y);
            }
#pragma unroll
            for (int p = 0; p < 4; p++) {
                uint32_t off = SWZ(vBase + (uint32_t)(ks * 16 * 128) + (uint32_t)(p * 32));
                uint32_t f[4];
                ldmatrix_x4_t(f, sb + 16384 + off);       // V hi
                mma16816(o[2*p],   ah, f[0], f[1]);
                mma16816(o[2*p],   al, f[0], f[1]);
                mma16816(o[2*p+1], ah, f[2], f[3]);
                mma16816(o[2*p+1], al, f[2], f[3]);
                ldmatrix_x4_t(f, sb + 24576 + off);       // V lo
                mma16816(o[2*p],   ah, f[0], f[1]);
                mma16816(o[2*p+1], ah, f[2], f[3]);
            }
        }
    }

    // ---- finalize: 1/l, write context as bf16 hi/lo [token][1024] ----
    l0 += __shfl_xor_sync(0xffffffffu, l0, 1);
    l0 += __shfl_xor_sync(0xffffffffu, l0, 2);
    l1 += __shfl_xor_sync(0xffffffffu, l1, 1);
    l1 += __shfl_xor_sync(0xffffffffu, l1, 2);
    float inv0 = 1.f / l0, inv1 = 1.f / l1;

    int r0g = q0w + (L >> 2), r1g = r0g + 8;
    size_t base0 = (size_t)(b * SEQ + r0g) * HID + h * HDIM + 2 * (L & 3);
    size_t base1 = (size_t)(b * SEQ + r1g) * HID + h * HDIM + 2 * (L & 3);
#pragma unroll
    for (int nb = 0; nb < 8; nb++) {
        float x0 = o[nb][0] * inv0, y0 = o[nb][1] * inv0;
        float x1 = o[nb][2] * inv1, y1 = o[nb][3] * inv1;
        __nv_bfloat162 hp0 = __floats2bfloat162_rn(x0, y0);
        __nv_bfloat162 hp1 = __floats2bfloat162_rn(x1, y1);
        float2 hf0 = __bfloat1622float2(hp0);
        float2 hf1 = __bfloat1622float2(hp1);
        __nv_bfloat162 lp0 = __floats2bfloat162_rn(x0 - hf0.x, y0 - hf0.y);
        __nv_bfloat162 lp1 = __floats2bfloat162_rn(x1 - hf1.x, y1 - hf1.y);
        *(__nv_bfloat162*)(Chi + base0 + nb * 8) = hp0;
        *(__nv_bfloat162*)(Clo + base0 + nb * 8) = lp0;
        *(__nv_bfloat162*)(Chi + base1 + nb * 8) = hp1;
        *(__nv_bfloat162*)(Clo + base1 + nb * 8) = lp1;
    }
}

// ---------------------------------------------------------------------------
extern "C" void kernel_launch(void* const* d_in, const int* in_sizes, int n_in,
                              void* d_out, int out_size)
{
    const float* hs     = (const float*)d_in[0];
    const int*   morpho = (const int*)  d_in[1];
    const float* Wq = (const float*)d_in[2];
    const float* bq = (const float*)d_in[3];
    const float* Wk = (const float*)d_in[4];
    const float* bk = (const float*)d_in[5];
    const float* Wv = (const float*)d_in[6];
    const float* bv = (const float*)d_in[7];
    const float* Wo = (const float*)d_in[8];
    const float* bo = (const float*)d_in[9];
    float* out = (float*)d_out;

    __nv_bfloat16 *ahi, *alo, *whi, *wlo;
    __nv_bfloat16 *qhi, *qlo, *khi, *klo, *vhi, *vlo;
    cudaGetSymbolAddress((void**)&ahi, g_Ahi);
    cudaGetSymbolAddress((void**)&alo, g_Alo);
    cudaGetSymbolAddress((void**)&whi, g_Whi);
    cudaGetSymbolAddress((void**)&wlo, g_Wlo);
    cudaGetSymbolAddress((void**)&qhi, g_Qhi);
    cudaGetSymbolAddress((void**)&qlo, g_Qlo);
    cudaGetSymbolAddress((void**)&khi, g_Khi);
    cudaGetSymbolAddress((void**)&klo, g_Klo);
    cudaGetSymbolAddress((void**)&vhi, g_Vhi);
    cudaGetSymbolAddress((void**)&vlo, g_Vlo);

    static bool attr_set = false;
    if (!attr_set) {
        cudaFuncSetAttribute(gemm_mma,
                             cudaFuncAttributeMaxDynamicSharedMemorySize, 65536);
        attr_set = true;
    }

    bias_kernel<<<BATCH, 256>>>(morpho);

    split_kernel<<<MTOT*HID/1024, 256>>>((const float4*)hs,
                                         (__nv_bfloat162*)ahi, (__nv_bfloat162*)alo);

    dim3 wtg(HID/32, HID/32), wtb(32, 8);
    wtrans_kernel<<<wtg, wtb>>>(Wq, whi + 0*HID*HID, wlo + 0*HID*HID);
    wtrans_kernel<<<wtg, wtb>>>(Wk, whi + 1*HID*HID, wlo + 1*HID*HID);
    wtrans_kernel<<<wtg, wtb>>>(Wv, whi + 2*HID*HID, wlo + 2*HID*HID);
    wtrans_kernel<<<wtg, wtb>>>(Wo, whi + 3*HID*HID, wlo + 3*HID*HID);

    dim3 gg(HID/128, MTOT/128);   // 8 x 32
    gemm_mma<<<gg, 256, 65536>>>(ahi, alo, whi + 0*HID*HID, wlo + 0*HID*HID,
                                 bq, nullptr, qhi, qlo, SCALE, 1);
    gemm_mma<<<gg, 256, 65536>>>(ahi, alo, whi + 1*HID*HID, wlo + 1*HID*HID,
                                 bk, nullptr, khi, klo, 1.0f, 1);
    gemm_mma<<<gg, 256, 65536>>>(ahi, alo, whi + 2*HID*HID, wlo + 2*HID*HID,
                                 bv, nullptr, vhi, vlo, 1.0f, 1);

    attn_mma<<<dim3(SEQ/128, NHEAD, BATCH), 256, 32768>>>(
        qhi, qlo, khi, klo, vhi, vlo, ahi, alo);

    gemm_mma<<<gg, 256, 65536>>>(ahi, alo, whi + 3*HID*HID, wlo + 3*HID*HID,
                                 bo, out, nullptr, nullptr, 1.0f, 0);
}

// round 9
// speedup vs baseline: 3.1761x; 1.7036x over previous
#include <cuda_runtime.h>
#include <cuda_bf16.h>
#include <cstdint>
#include <math.h>

#define BATCH 4
#define SEQ   1024
#define HID   1024
#define NHEAD 16
#define HDIM  64
#define SCALE 0.125f
#define MTOT  (BATCH*SEQ)

// ------------------------- scratch (device globals) -------------------------
__device__ __nv_bfloat16 g_Ahi[MTOT*HID];        // hi/lo split of GEMM A input
__device__ __nv_bfloat16 g_Alo[MTOT*HID];
__device__ __nv_bfloat16 g_Whi[4*HID*HID];       // transposed weights [N][K], 4 slots
__device__ __nv_bfloat16 g_Wlo[4*HID*HID];
// Q/K/V bf16 hi/lo, head-major [b][h][s][d]
__device__ __nv_bfloat16 g_Qhi[MTOT*HID];
__device__ __nv_bfloat16 g_Qlo[MTOT*HID];
__device__ __nv_bfloat16 g_Khi[MTOT*HID];
__device__ __nv_bfloat16 g_Klo[MTOT*HID];
__device__ __nv_bfloat16 g_Vhi[MTOT*HID];
__device__ __nv_bfloat16 g_Vlo[MTOT*HID];
__device__ int   g_nearest[BATCH*SEQ];
__device__ float g_colbias[BATCH*SEQ];

// ------------------------------ PTX helpers ---------------------------------
__device__ __forceinline__ uint32_t smem_u32(const void* p) {
    uint32_t a;
    asm("{ .reg .u64 t; cvta.to.shared.u64 t, %1; cvt.u32.u64 %0, t; }"
        : "=r"(a) : "l"(p));
    return a;
}

__device__ __forceinline__ void cp_async16(uint32_t saddr, const void* gaddr) {
    asm volatile("cp.async.cg.shared.global [%0], [%1], 16;"
                 :: "r"(saddr), "l"(gaddr) : "memory");
}

__device__ __forceinline__ void ldmatrix_x4(uint32_t* r, uint32_t addr) {
    asm volatile("ldmatrix.sync.aligned.m8n8.x4.shared.b16 {%0,%1,%2,%3}, [%4];"
                 : "=r"(r[0]), "=r"(r[1]), "=r"(r[2]), "=r"(r[3]) : "r"(addr));
}

__device__ __forceinline__ void ldmatrix_x4_t(uint32_t* r, uint32_t addr) {
    asm volatile("ldmatrix.sync.aligned.m8n8.x4.trans.shared.b16 {%0,%1,%2,%3}, [%4];"
                 : "=r"(r[0]), "=r"(r[1]), "=r"(r[2]), "=r"(r[3]) : "r"(addr));
}

__device__ __forceinline__ void mma16816(float* d, const uint32_t* a,
                                         uint32_t b0, uint32_t b1) {
    asm volatile(
        "mma.sync.aligned.m16n8k16.row.col.f32.bf16.bf16.f32 "
        "{%0,%1,%2,%3}, {%4,%5,%6,%7}, {%8,%9}, {%0,%1,%2,%3};"
        : "+f"(d[0]), "+f"(d[1]), "+f"(d[2]), "+f"(d[3])
        : "r"(a[0]), "r"(a[1]), "r"(a[2]), "r"(a[3]), "r"(b0), "r"(b1));
}

#define SWZ(x) ((x) ^ (((x) >> 3) & 0x70))

__device__ __forceinline__ uint32_t pack_bf2(float x, float y) {
    __nv_bfloat162 h = __floats2bfloat162_rn(x, y);
    return *(uint32_t*)&h;
}

// ---------------------------------------------------------------------------
// Morphological bias precompute (parallelized: 32 blocks)
// ---------------------------------------------------------------------------
__global__ void bias_kernel(const int* __restrict__ morpho)
{
    int b = blockIdx.x;
    __shared__ int types[SEQ];
    for (int i = threadIdx.x; i < SEQ; i += blockDim.x)
        types[i] = morpho[b*SEQ + i];
    __syncthreads();
    int q = blockIdx.y * 128 + threadIdx.x;
    int best = -1;
    int bestd = 1 << 30;
    for (int j = 0; j < SEQ; j++) {
        if (types[j] == 2) {
            int d = abs(q - j);
            if (d < bestd) { bestd = d; best = j; }
        }
    }
    g_nearest[b*SEQ + q] = best;
    int t = types[q];
    float cb = 0.0f;
    if (t == 0) cb = 0.75f;
    else if (t == 1) cb = 0.36f;
    g_colbias[b*SEQ + q] = cb;
}

// ---------------------------------------------------------------------------
// fp32 -> bf16 hi/lo split (row-major, vectorized by 4)
// ---------------------------------------------------------------------------
__global__ void __launch_bounds__(256) split_kernel(
    const float4* __restrict__ src, __nv_bfloat162* __restrict__ hi,
    __nv_bfloat162* __restrict__ lo)
{
    int i = blockIdx.x * 256 + threadIdx.x;
    float4 v = src[i];
    __nv_bfloat16 h0 = __float2bfloat16(v.x);
    __nv_bfloat16 h1 = __float2bfloat16(v.y);
    __nv_bfloat16 h2 = __float2bfloat16(v.z);
    __nv_bfloat16 h3 = __float2bfloat16(v.w);
    __nv_bfloat162 ha; ha.x = h0; ha.y = h1;
    __nv_bfloat162 hb; hb.x = h2; hb.y = h3;
    hi[2*i] = ha; hi[2*i+1] = hb;
    __nv_bfloat162 la, lb;
    la.x = __float2bfloat16(v.x - __bfloat162float(h0));
    la.y = __float2bfloat16(v.y - __bfloat162float(h1));
    lb.x = __float2bfloat16(v.z - __bfloat162float(h2));
    lb.y = __float2bfloat16(v.w - __bfloat162float(h3));
    lo[2*i] = la; lo[2*i+1] = lb;
}

// ---------------------------------------------------------------------------
// W [K][N] fp32 -> Wt hi/lo [N][K] bf16 (transpose + split), z = weight slot
// ---------------------------------------------------------------------------
__global__ void wtrans_kernel(const float* __restrict__ W0,
                              const float* __restrict__ W1,
                              const float* __restrict__ W2,
                              const float* __restrict__ W3,
                              __nv_bfloat16* __restrict__ hiB,
                              __nv_bfloat16* __restrict__ loB)
{
    int z = blockIdx.z;
    const float* W = (z == 0) ? W0 : (z == 1) ? W1 : (z == 2) ? W2 : W3;
    __nv_bfloat16* hi = hiB + (size_t)z * HID * HID;
    __nv_bfloat16* lo = loB + (size_t)z * HID * HID;

    __shared__ float t[32][33];
    int n0 = blockIdx.x * 32, k0 = blockIdx.y * 32;
    int c = threadIdx.x, r0 = threadIdx.y;        // 32 x 8
#pragma unroll
    for (int i = 0; i < 4; i++)
        t[r0 + 8*i][c] = W[(size_t)(k0 + r0 + 8*i) * HID + n0 + c];
    __syncthreads();
#pragma unroll
    for (int i = 0; i < 4; i++) {
        int rr = r0 + 8*i;
        float v = t[c][rr];
        __nv_bfloat16 h = __float2bfloat16(v);
        hi[(size_t)(n0 + rr) * HID + k0 + c] = h;
        lo[(size_t)(n0 + rr) * HID + k0 + c] =
            __float2bfloat16(v - __bfloat162float(h));
    }
}

// ---------------------------------------------------------------------------
// Shared GEMM mainloop (bf16-split 3-term, 128x128 CTA tile, 8 warps)
// ---------------------------------------------------------------------------
__device__ __forceinline__ void gemm_core(
    const __nv_bfloat16* __restrict__ Ahi, const __nv_bfloat16* __restrict__ Alo,
    const __nv_bfloat16* __restrict__ Bhi, const __nv_bfloat16* __restrict__ Blo,
    int bm, int bn, uint32_t sbase, float acc[4][4][4])
{
    const int tid = threadIdx.x;
    const int L = tid & 31;
    const int wid = tid >> 5;
    const int wm = wid >> 2;
    const int wn = wid & 3;

    const int ldrow = tid >> 1;
    const int ldcu  = (tid & 1) * 4;

    uint32_t aRow = (uint32_t)(wm * 64 + (L & 15)) * 128 + ((L >> 4) << 4);
    uint32_t bRow = (uint32_t)(wn * 32 + (L & 7) + ((L >> 4) & 1) * 8) * 128
                  + (((L >> 3) & 1) << 4);

    auto loadChunk = [&](int it) {
        int pass = it >> 4;
        int k0 = (it & 15) << 6;
        int buf = it & 1;
        const __nv_bfloat16* Ap = (pass == 2) ? Alo : Ahi;
        const __nv_bfloat16* Bp = (pass == 1) ? Blo : Bhi;
        uint32_t sa = sbase + buf * 16384;
        uint32_t sb = sbase + 32768 + buf * 16384;
#pragma unroll
        for (int i = 0; i < 4; i++) {
            uint32_t off = (uint32_t)(ldrow * 128) + ((ldcu + i) << 4);
            uint32_t sw = SWZ(off);
            cp_async16(sa + sw, Ap + (size_t)(bm + ldrow) * HID + k0 + ((ldcu + i) << 3));
            cp_async16(sb + sw, Bp + (size_t)(bn + ldrow) * HID + k0 + ((ldcu + i) << 3));
        }
    };

    loadChunk(0);
    asm volatile("cp.async.commit_group;" ::: "memory");

    for (int it = 0; it < 48; it++) {
        asm volatile("cp.async.wait_group 0;" ::: "memory");
        __syncthreads();
        if (it + 1 < 48) {
            loadChunk(it + 1);
            asm volatile("cp.async.commit_group;" ::: "memory");
        }

        int buf = it & 1;
        uint32_t sa = sbase + buf * 16384;
        uint32_t sb = sbase + 32768 + buf * 16384;

#pragma unroll
        for (int ks = 0; ks < 4; ks++) {
            uint32_t a[4][4], b[2][4];
#pragma unroll
            for (int mt = 0; mt < 4; mt++) {
                uint32_t off = aRow + (uint32_t)(mt * 16 * 128) + (uint32_t)(ks * 32);
                ldmatrix_x4(a[mt], sa + SWZ(off));
            }
#pragma unroll
            for (int p = 0; p < 2; p++) {
                uint32_t off = bRow + (uint32_t)(p * 16 * 128) + (uint32_t)(ks * 32);
                ldmatrix_x4(b[p], sb + SWZ(off));
            }
#pragma unroll
            for (int mt = 0; mt < 4; mt++)
#pragma unroll
                for (int nt = 0; nt < 4; nt++)
                    mma16816(acc[mt][nt], a[mt],
                             b[nt >> 1][(nt & 1) * 2], b[nt >> 1][(nt & 1) * 2 + 1]);
        }
    }
}

// ---------------------------------------------------------------------------
// Fused QKV projection: blockIdx.z in {0,1,2} selects weight/bias/dest.
// Epilogue: (acc+bias)*scale -> bf16 hi/lo, head-major [b][h][s][d].
// ---------------------------------------------------------------------------
__global__ void __launch_bounds__(256) gemm_qkv(
    const __nv_bfloat16* __restrict__ Ahi, const __nv_bfloat16* __restrict__ Alo,
    const __nv_bfloat16* __restrict__ WhiB, const __nv_bfloat16* __restrict__ WloB,
    const float* __restrict__ bq, const float* __restrict__ bk,
    const float* __restrict__ bv,
    __nv_bfloat16* __restrict__ qhi, __nv_bfloat16* __restrict__ qlo,
    __nv_bfloat16* __restrict__ khi, __nv_bfloat16* __restrict__ klo,
    __nv_bfloat16* __restrict__ vhi, __nv_bfloat16* __restrict__ vlo)
{
    extern __shared__ __align__(1024) char smem[];
    const int z = blockIdx.z;
    const __nv_bfloat16* Bhi = WhiB + (size_t)z * HID * HID;
    const __nv_bfloat16* Blo = WloB + (size_t)z * HID * HID;
    const float* bias = (z == 0) ? bq : (z == 1) ? bk : bv;
    __nv_bfloat16* Chi = (z == 0) ? qhi : (z == 1) ? khi : vhi;
    __nv_bfloat16* Clo = (z == 0) ? qlo : (z == 1) ? klo : vlo;
    const float scale = (z == 0) ? SCALE : 1.0f;

    const int bm = blockIdx.y * 128, bn = blockIdx.x * 128;

    float acc[4][4][4];
#pragma unroll
    for (int i = 0; i < 4; i++)
#pragma unroll
        for (int j = 0; j < 4; j++)
#pragma unroll
            for (int k = 0; k < 4; k++) acc[i][j][k] = 0.f;

    gemm_core(Ahi, Alo, Bhi, Blo, bm, bn, smem_u32(smem), acc);

    const int tid = threadIdx.x, L = tid & 31, wid = tid >> 5;
    const int wm = wid >> 2, wn = wid & 3;
    const int r = L >> 2, c2 = (L & 3) * 2;
#pragma unroll
    for (int mt = 0; mt < 4; mt++) {
        int gm0 = bm + wm * 64 + mt * 16 + r;
#pragma unroll
        for (int nt = 0; nt < 4; nt++) {
            int gn = bn + wn * 32 + nt * 8 + c2;
            float b0 = bias[gn], b1 = bias[gn + 1];
            float v00 = (acc[mt][nt][0] + b0) * scale;
            float v01 = (acc[mt][nt][1] + b1) * scale;
            float v10 = (acc[mt][nt][2] + b0) * scale;
            float v11 = (acc[mt][nt][3] + b1) * scale;
            int hh = gn >> 6, d = gn & 63;
#pragma unroll
            for (int half = 0; half < 2; half++) {
                int gm = gm0 + half * 8;
                float x = half ? v10 : v00, y = half ? v11 : v01;
                int bb = gm >> 10, s = gm & 1023;
                size_t idx = ((size_t)((bb * NHEAD + hh) * SEQ) + s) * HDIM + d;
                __nv_bfloat162 hp = __floats2bfloat162_rn(x, y);
                float2 hf = __bfloat1622float2(hp);
                __nv_bfloat162 lp = __floats2bfloat162_rn(x - hf.x, y - hf.y);
                *(__nv_bfloat162*)(Chi + idx) = hp;
                *(__nv_bfloat162*)(Clo + idx) = lp;
            }
        }
    }
}

// ---------------------------------------------------------------------------
// Output projection: fp32 row-major destination.
// ---------------------------------------------------------------------------
__global__ void __launch_bounds__(256) gemm_out(
    const __nv_bfloat16* __restrict__ Ahi, const __nv_bfloat16* __restrict__ Alo,
    const __nv_bfloat16* __restrict__ Bhi, const __nv_bfloat16* __restrict__ Blo,
    const float* __restrict__ bias, float* __restrict__ C)
{
    extern __shared__ __align__(1024) char smem[];
    const int bm = blockIdx.y * 128, bn = blockIdx.x * 128;

    float acc[4][4][4];
#pragma unroll
    for (int i = 0; i < 4; i++)
#pragma unroll
        for (int j = 0; j < 4; j++)
#pragma unroll
            for (int k = 0; k < 4; k++) acc[i][j][k] = 0.f;

    gemm_core(Ahi, Alo, Bhi, Blo, bm, bn, smem_u32(smem), acc);

    const int tid = threadIdx.x, L = tid & 31, wid = tid >> 5;
    const int wm = wid >> 2, wn = wid & 3;
    const int r = L >> 2, c2 = (L & 3) * 2;
#pragma unroll
    for (int mt = 0; mt < 4; mt++) {
        int gm0 = bm + wm * 64 + mt * 16 + r;
#pragma unroll
        for (int nt = 0; nt < 4; nt++) {
            int gn = bn + wn * 32 + nt * 8 + c2;
            float b0 = bias[gn], b1 = bias[gn + 1];
            float2 w0, w1;
            w0.x = acc[mt][nt][0] + b0; w0.y = acc[mt][nt][1] + b1;
            w1.x = acc[mt][nt][2] + b0; w1.y = acc[mt][nt][3] + b1;
            *(float2*)(C + (size_t)gm0 * HID + gn) = w0;
            *(float2*)(C + (size_t)(gm0 + 8) * HID + gn) = w1;
        }
    }
}

// ---------------------------------------------------------------------------
// Tensor-core flash attention, bf16-split, DOUBLE-BUFFERED KV tiles.
// CTA = 128 q-rows x one (b,h); 8 warps; KV tile = 64. 64KB dynamic smem.
// ---------------------------------------------------------------------------
__global__ void __launch_bounds__(256) attn_mma(
    const __nv_bfloat16* __restrict__ Qhi, const __nv_bfloat16* __restrict__ Qlo,
    const __nv_bfloat16* __restrict__ Khi, const __nv_bfloat16* __restrict__ Klo,
    const __nv_bfloat16* __restrict__ Vhi, const __nv_bfloat16* __restrict__ Vlo,
    __nv_bfloat16* __restrict__ Chi, __nv_bfloat16* __restrict__ Clo)
{
    extern __shared__ __align__(1024) char smem[];   // 64 KB: buf0/buf1 32KB each
    __shared__ float sCB[2][64];

    const int tid = threadIdx.x, L = tid & 31, wid = tid >> 5;
    const int b = blockIdx.z, h = blockIdx.y;
    const int qcta = blockIdx.x * 128;
    const int q0w = qcta + wid * 16;
    const uint32_t sb = smem_u32(smem);
    const size_t headbase = ((size_t)(b * NHEAD + h)) * SEQ;

    // ---- stage Q tile (128x64 hi+lo) through buf0 into A-fragments ----
    {
        const __nv_bfloat16* qh = Qhi + (headbase + qcta) * HDIM;
        const __nv_bfloat16* ql = Qlo + (headbase + qcta) * HDIM;
#pragma unroll
        for (int i = 0; i < 4; i++) {
            int u = tid + i * 256;
            int row = u >> 3, cu = u & 7;
            uint32_t sw = SWZ((uint32_t)(row * 128 + cu * 16));
            cp_async16(sb + sw, qh + (size_t)row * HDIM + cu * 8);
            cp_async16(sb + 16384 + sw, ql + (size_t)row * HDIM + cu * 8);
        }
        asm volatile("cp.async.commit_group;" ::: "memory");
        asm volatile("cp.async.wait_group 0;" ::: "memory");
        __syncthreads();
    }
    uint32_t qh[4][4], ql[4][4];
    {
        uint32_t base = (uint32_t)((wid * 16 + (L & 15)) * 128 + ((L >> 4) << 4));
#pragma unroll
        for (int ks = 0; ks < 4; ks++) {
            uint32_t off = SWZ(base + ks * 32);
            ldmatrix_x4(qh[ks], sb + off);
            ldmatrix_x4(ql[ks], sb + 16384 + off);
        }
    }
    __syncthreads();   // Q fully consumed; buffers free for KV

    const int nr0 = g_nearest[b * SEQ + q0w + (L >> 2)];
    const int nr1 = g_nearest[b * SEQ + q0w + (L >> 2) + 8];

    float o[8][4];
#pragma unroll
    for (int i = 0; i < 8; i++)
#pragma unroll
        for (int j = 0; j < 4; j++) o[i][j] = 0.f;
    float m0 = -1e30f, m1 = -1e30f, l0 = 0.f, l1 = 0.f;

    uint32_t kBase = (uint32_t)((L & 7) + ((L >> 4) & 1) * 8) * 128
                   + (((L >> 3) & 1) << 4);
    uint32_t vBase = (uint32_t)((L & 7) + ((L >> 3) & 1) * 8) * 128
                   + ((L >> 4) << 4);

    auto issueTile = [&](int t) {
        int buf = t & 1;
        uint32_t base = sb + buf * 32768;
        int kt = t * 64;
        const __nv_bfloat16* kh = Khi + (headbase + kt) * HDIM;
        const __nv_bfloat16* kl = Klo + (headbase + kt) * HDIM;
        const __nv_bfloat16* vh = Vhi + (headbase + kt) * HDIM;
        const __nv_bfloat16* vl = Vlo + (headbase + kt) * HDIM;
#pragma unroll
        for (int i = 0; i < 2; i++) {
            int u = tid + i * 256;
            int row = u >> 3, cu = u & 7;
            uint32_t sw = SWZ((uint32_t)(row * 128 + cu * 16));
            size_t g = (size_t)row * HDIM + cu * 8;
            cp_async16(base + sw,         kh + g);
            cp_async16(base +  8192 + sw, kl + g);
            cp_async16(base + 16384 + sw, vh + g);
            cp_async16(base + 24576 + sw, vl + g);
        }
        if (tid < 64) sCB[buf][tid] = g_colbias[b * SEQ + kt + tid];
        asm volatile("cp.async.commit_group;" ::: "memory");
    };

    issueTile(0);
    issueTile(1);

    for (int it = 0; it < 16; it++) {
        if (it + 1 < 16)
            asm volatile("cp.async.wait_group 1;" ::: "memory");
        else
            asm volatile("cp.async.wait_group 0;" ::: "memory");
        __syncthreads();

        const int buf = it & 1;
        const uint32_t base = sb + buf * 32768;
        const int kt = it * 64;

        // ---- S = Qh*Kh + Qh*Kl + Ql*Kh ----
        float s[8][4];
#pragma unroll
        for (int i = 0; i < 8; i++)
#pragma unroll
            for (int j = 0; j < 4; j++) s[i][j] = 0.f;

#pragma unroll
        for (int ks = 0; ks < 4; ks++) {
#pragma unroll
            for (int p = 0; p < 4; p++) {
                uint32_t off = SWZ(kBase + (uint32_t)(p * 16 * 128) + (uint32_t)(ks * 32));
                uint32_t f[4];
                ldmatrix_x4(f, base + off);                 // K hi
                mma16816(s[2*p],   qh[ks], f[0], f[1]);
                mma16816(s[2*p],   ql[ks], f[0], f[1]);
                mma16816(s[2*p+1], qh[ks], f[2], f[3]);
                mma16816(s[2*p+1], ql[ks], f[2], f[3]);
                ldmatrix_x4(f, base + 8192 + off);          // K lo
                mma16816(s[2*p],   qh[ks], f[0], f[1]);
                mma16816(s[2*p+1], qh[ks], f[2], f[3]);
            }
        }

        // ---- bias + online softmax ----
        int colb = kt + 2 * (L & 3);
        float t0 = -1e30f, t1 = -1e30f;
#pragma unroll
        for (int nb = 0; nb < 8; nb++) {
            float c0 = sCB[buf][nb * 8 + 2 * (L & 3)];
            float c1 = sCB[buf][nb * 8 + 2 * (L & 3) + 1];
            int g0 = colb + nb * 8, g1 = g0 + 1;
            s[nb][0] += c0 + (g0 == nr0 ? 2.f : 0.f);
            s[nb][1] += c1 + (g1 == nr0 ? 2.f : 0.f);
            s[nb][2] += c0 + (g0 == nr1 ? 2.f : 0.f);
            s[nb][3] += c1 + (g1 == nr1 ? 2.f : 0.f);
            t0 = fmaxf(t0, fmaxf(s[nb][0], s[nb][1]));
            t1 = fmaxf(t1, fmaxf(s[nb][2], s[nb][3]));
        }
        t0 = fmaxf(t0, __shfl_xor_sync(0xffffffffu, t0, 1));
        t0 = fmaxf(t0, __shfl_xor_sync(0xffffffffu, t0, 2));
        t1 = fmaxf(t1, __shfl_xor_sync(0xffffffffu, t1, 1));
        t1 = fmaxf(t1, __shfl_xor_sync(0xffffffffu, t1, 2));
        float nm0 = fmaxf(m0, t0), nm1 = fmaxf(m1, t1);
        float cr0 = __expf(m0 - nm0), cr1 = __expf(m1 - nm1);
        m0 = nm0; m1 = nm1;
        l0 *= cr0; l1 *= cr1;
#pragma unroll
        for (int nb = 0; nb < 8; nb++) {
            o[nb][0] *= cr0; o[nb][1] *= cr0;
            o[nb][2] *= cr1; o[nb][3] *= cr1;
            s[nb][0] = __expf(s[nb][0] - m0); l0 += s[nb][0];
            s[nb][1] = __expf(s[nb][1] - m0); l0 += s[nb][1];
            s[nb][2] = __expf(s[nb][2] - m1); l1 += s[nb][2];
            s[nb][3] = __expf(s[nb][3] - m1); l1 += s[nb][3];
        }

        // ---- O += Ph*Vh + Ph*Vl + Pl*Vh ----
#pragma unroll
        for (int ks = 0; ks < 4; ks++) {
            uint32_t ah[4], al[4];
#pragma unroll
            for (int half = 0; half < 2; half++) {
                int nb = 2 * ks + half;
                __nv_bfloat162 h01 = __floats2bfloat162_rn(s[nb][0], s[nb][1]);
                __nv_bfloat162 h23 = __floats2bfloat162_rn(s[nb][2], s[nb][3]);
                float2 f01 = __bfloat1622float2(h01);
                float2 f23 = __bfloat1622float2(h23);
                ah[2*half]   = *(uint32_t*)&h01;
                ah[2*half+1] = *(uint32_t*)&h23;
                al[2*half]   = pack_bf2(s[nb][0] - f01.x, s[nb][1] - f01.y);
                al[2*half+1] = pack_bf2(s[nb][2] - f23.x, s[nb][3] - f23.y);
            }
#pragma unroll
            for (int p = 0; p < 4; p++) {
                uint32_t off = SWZ(vBase + (uint32_t)(ks * 16 * 128) + (uint32_t)(p * 32));
                uint32_t f[4];
                ldmatrix_x4_t(f, base + 16384 + off);       // V hi
                mma16816(o[2*p],   ah, f[0], f[1]);
                mma16816(o[2*p],   al, f[0], f[1]);
                mma16816(o[2*p+1], ah, f[2], f[3]);
                mma16816(o[2*p+1], al, f[2], f[3]);
                ldmatrix_x4_t(f, base + 24576 + off);       // V lo
                mma16816(o[2*p],   ah, f[0], f[1]);
                mma16816(o[2*p+1], ah, f[2], f[3]);
            }
        }

        __syncthreads();                 // all warps done with buf
        if (it + 2 < 16) issueTile(it + 2);
    }

    // ---- finalize ----
    l0 += __shfl_xor_sync(0xffffffffu, l0, 1);
    l0 += __shfl_xor_sync(0xffffffffu, l0, 2);
    l1 += __shfl_xor_sync(0xffffffffu, l1, 1);
    l1 += __shfl_xor_sync(0xffffffffu, l1, 2);
    float inv0 = 1.f / l0, inv1 = 1.f / l1;

    int r0g = q0w + (L >> 2), r1g = r0g + 8;
    size_t base0 = (size_t)(b * SEQ + r0g) * HID + h * HDIM + 2 * (L & 3);
    size_t base1 = (size_t)(b * SEQ + r1g) * HID + h * HDIM + 2 * (L & 3);
#pragma unroll
    for (int nb = 0; nb < 8; nb++) {
        float x0 = o[nb][0] * inv0, y0 = o[nb][1] * inv0;
        float x1 = o[nb][2] * inv1, y1 = o[nb][3] * inv1;
        __nv_bfloat162 hp0 = __floats2bfloat162_rn(x0, y0);
        __nv_bfloat162 hp1 = __floats2bfloat162_rn(x1, y1);
        float2 hf0 = __bfloat1622float2(hp0);
        float2 hf1 = __bfloat1622float2(hp1);
        __nv_bfloat162 lp0 = __floats2bfloat162_rn(x0 - hf0.x, y0 - hf0.y);
        __nv_bfloat162 lp1 = __floats2bfloat162_rn(x1 - hf1.x, y1 - hf1.y);
        *(__nv_bfloat162*)(Chi + base0 + nb * 8) = hp0;
        *(__nv_bfloat162*)(Clo + base0 + nb * 8) = lp0;
        *(__nv_bfloat162*)(Chi + base1 + nb * 8) = hp1;
        *(__nv_bfloat162*)(Clo + base1 + nb * 8) = lp1;
    }
}

// ---------------------------------------------------------------------------
extern "C" void kernel_launch(void* const* d_in, const int* in_sizes, int n_in,
                              void* d_out, int out_size)
{
    const float* hs     = (const float*)d_in[0];
    const int*   morpho = (const int*)  d_in[1];
    const float* Wq = (const float*)d_in[2];
    const float* bq = (const float*)d_in[3];
    const float* Wk = (const float*)d_in[4];
    const float* bk = (const float*)d_in[5];
    const float* Wv = (const float*)d_in[6];
    const float* bv = (const float*)d_in[7];
    const float* Wo = (const float*)d_in[8];
    const float* bo = (const float*)d_in[9];
    float* out = (float*)d_out;

    __nv_bfloat16 *ahi, *alo, *whi, *wlo;
    __nv_bfloat16 *qhi, *qlo, *khi, *klo, *vhi, *vlo;
    cudaGetSymbolAddress((void**)&ahi, g_Ahi);
    cudaGetSymbolAddress((void**)&alo, g_Alo);
    cudaGetSymbolAddress((void**)&whi, g_Whi);
    cudaGetSymbolAddress((void**)&wlo, g_Wlo);
    cudaGetSymbolAddress((void**)&qhi, g_Qhi);
    cudaGetSymbolAddress((void**)&qlo, g_Qlo);
    cudaGetSymbolAddress((void**)&khi, g_Khi);
    cudaGetSymbolAddress((void**)&klo, g_Klo);
    cudaGetSymbolAddress((void**)&vhi, g_Vhi);
    cudaGetSymbolAddress((void**)&vlo, g_Vlo);

    static bool attr_set = false;
    if (!attr_set) {
        cudaFuncSetAttribute(gemm_qkv,
                             cudaFuncAttributeMaxDynamicSharedMemorySize, 65536);
        cudaFuncSetAttribute(gemm_out,
                             cudaFuncAttributeMaxDynamicSharedMemorySize, 65536);
        cudaFuncSetAttribute(attn_mma,
                             cudaFuncAttributeMaxDynamicSharedMemorySize, 65536);
        attr_set = true;
    }

    bias_kernel<<<dim3(BATCH, SEQ/128), 128>>>(morpho);

    split_kernel<<<MTOT*HID/1024, 256>>>((const float4*)hs,
                                         (__nv_bfloat162*)ahi, (__nv_bfloat162*)alo);

    wtrans_kernel<<<dim3(HID/32, HID/32, 4), dim3(32, 8)>>>(
        Wq, Wk, Wv, Wo, whi, wlo);

    gemm_qkv<<<dim3(HID/128, MTOT/128, 3), 256, 65536>>>(
        ahi, alo, whi, wlo, bq, bk, bv, qhi, qlo, khi, klo, vhi, vlo);

    attn_mma<<<dim3(SEQ/128, NHEAD, BATCH), 256, 65536>>>(
        qhi, qlo, khi, klo, vhi, vlo, ahi, alo);

    gemm_out<<<dim3(HID/128, MTOT/128), 256, 65536>>>(
        ahi, alo, whi + 3*(size_t)HID*HID, wlo + 3*(size_t)HID*HID, bo, out);
}